// round 1
// baseline (speedup 1.0000x reference)
#include <cuda_runtime.h>

// LTU_5918464934238: binary-threshold GEMV.
// out[i] = (W[i]·x < 0.6*4096 - count(W[i]<0)) ? 0 : 1
// Fused: t_i = W[i]·x + count(W[i]<0);  out[i] = (t_i < 2457.60009765625f) ? 0 : 1
//
// HBM-bound: one 128 MB streaming read of W. x (16 KB) staged in smem once
// per block and reused across the block's rows.

#define LTU_THREADS 256
#define LTU_NINP    4096
#define LTU_VECS    (LTU_NINP / 4)          // 1024 float4 per row
#define LTU_VPT     (LTU_VECS / LTU_THREADS) // 4 float4 per thread per row

__global__ __launch_bounds__(LTU_THREADS)
void ltu_kernel(const float* __restrict__ x,
                const float* __restrict__ W,
                float* __restrict__ out,
                int rows)
{
    __shared__ float4 xs[LTU_VECS];          // 16 KB
    __shared__ float  wsum[LTU_THREADS / 32];

    // Stage x once per block (hits L2; tiny vs W traffic).
    const float4* xv = reinterpret_cast<const float4*>(x);
    for (int i = threadIdx.x; i < LTU_VECS; i += LTU_THREADS)
        xs[i] = xv[i];
    __syncthreads();

    const int lane = threadIdx.x & 31;
    const int warp = threadIdx.x >> 5;

    for (int row = blockIdx.x; row < rows; row += gridDim.x) {
        const float4* Wr = reinterpret_cast<const float4*>(W)
                           + (size_t)row * LTU_VECS;
        float t = 0.0f;
        #pragma unroll
        for (int i = 0; i < LTU_VPT; i++) {
            const int idx = threadIdx.x + i * LTU_THREADS; // coalesced LDG.128
            const float4 w = Wr[idx];
            const float4 v = xs[idx];
            // score term
            t = fmaf(w.x, v.x, t);
            t = fmaf(w.y, v.y, t);
            t = fmaf(w.z, v.z, t);
            t = fmaf(w.w, v.w, t);
            // negative-count term (folded into the same accumulator)
            t += (w.x < 0.0f ? 1.0f : 0.0f);
            t += (w.y < 0.0f ? 1.0f : 0.0f);
            t += (w.z < 0.0f ? 1.0f : 0.0f);
            t += (w.w < 0.0f ? 1.0f : 0.0f);
        }

        // intra-warp reduce
        #pragma unroll
        for (int o = 16; o > 0; o >>= 1)
            t += __shfl_xor_sync(0xffffffffu, t, o);

        if (lane == 0) wsum[warp] = t;
        __syncthreads();

        if (warp == 0) {
            float s = (lane < (LTU_THREADS / 32)) ? wsum[lane] : 0.0f;
            #pragma unroll
            for (int o = (LTU_THREADS / 64); o > 0; o >>= 1)
                s += __shfl_xor_sync(0xffffffffu, s, o);
            if (lane == 0) {
                // tau_base = float(0.6f) * 4096 = 2457.60009765625 exactly
                const float tau_base = 0.6f * 4096.0f;
                out[row] = (s < tau_base) ? 0.0f : 1.0f;
            }
        }
        __syncthreads();   // protect wsum before next row's writes
    }
}

extern "C" void kernel_launch(void* const* d_in, const int* in_sizes, int n_in,
                              void* d_out, int out_size)
{
    // metadata order: input (4096), weight (8192*4096). Defensive swap if
    // the smaller buffer isn't first.
    const float* x = (const float*)d_in[0];
    const float* W = (const float*)d_in[1];
    if (n_in >= 2 && in_sizes[0] > in_sizes[1]) {
        x = (const float*)d_in[1];
        W = (const float*)d_in[0];
    }
    float* out = (float*)d_out;
    const int rows = out_size;               // 8192

    // 148 SMs * 8 blocks: each block handles ~7 rows, staging x once.
    const int grid = 1184;
    ltu_kernel<<<grid, LTU_THREADS>>>(x, W, out, rows);
}